// round 3
// baseline (speedup 1.0000x reference)
#include <cuda_runtime.h>
#include <cuda_fp16.h>

// QuantizedBatchNorm3d: x [8,64,32,64,64] fp32, weight[64], bias[64] -> y same shape.
// fake_quant(exp=5, sig=10, RNE) == IEEE fp16 round-trip for all reachable values.
//
// R3: pass1 materializes x_q as fp16 (128MB) while reducing; x reads are
// evict-first so L2 retains the fp16 buffer. Pass3 reads x_q (mostly L2 hits,
// backward walk) and DISCARDs each consumed L2 line (no DRAM writeback).
// DRAM traffic drops from ~768MB to ~520-560MB.

#define NB        8
#define NC        64
#define SPATIAL   (32*64*64)            // 131072 = 2^17, per (n,c) slice
#define CPC       (NB*SPATIAL)          // 2^20 elements per channel
#define TOTAL_EL  (1 << 26)
#define TOTAL_V4  (1 << 24)             // float4 count
#define NGROUPS   (1 << 23)             // 8-element groups for pass3
#define BPC       32                    // reduce blocks per channel
#define RTHREADS  256

__device__ float  g_psum[NC * BPC];
__device__ float  g_psq [NC * BPC];
__device__ float4 g_params[NC];         // {mean_q, inv_std, w_q, b_q}
__device__ __align__(128) __half g_xq[TOTAL_EL];   // 128 MB scratch: fake-quantized x

__device__ __forceinline__ float fq1(float v) {
    return __half2float(__float2half_rn(v));
}
__device__ __forceinline__ float2 fq2(float a, float b) {
    __half2 h = __floats2half2_rn(a, b);
    return __half22float2(h);
}
__device__ __forceinline__ unsigned h2u(__half2 h) {
    unsigned u; __builtin_memcpy(&u, &h, 4); return u;
}
__device__ __forceinline__ __half2 u2h(unsigned u) {
    __half2 h; __builtin_memcpy(&h, &u, 4); return h;
}

// ------- Pass 1: per-channel sum/sumsq of fq(x); materialize x_q as fp16 -------
__global__ void __launch_bounds__(RTHREADS) qbn_reduce(const float* __restrict__ x) {
    const int c   = blockIdx.y;
    const int bx  = blockIdx.x;
    const int tid = threadIdx.x;

    const int VEC_PER_N = SPATIAL / 4;          // 32768 float4 per (n,c) slice
    const int stride    = BPC * RTHREADS;       // 8192
    const int start     = bx * RTHREADS + tid;

    uint2* xq = reinterpret_cast<uint2*>(g_xq); // 4 halves per uint2

    float s = 0.f, sq = 0.f;
    #pragma unroll
    for (int n = 0; n < NB; n++) {
        const size_t slice_v4 = (size_t)(n * NC + c) * VEC_PER_N;
        const float4* p = reinterpret_cast<const float4*>(x) + slice_v4;
        #pragma unroll
        for (int i = 0; i < VEC_PER_N / stride; i++) {   // 4 iters
            const int off = start + i * stride;
            float4 v = __ldcs(p + off);                  // dead after read
            __half2 h0 = __floats2half2_rn(v.x, v.y);
            __half2 h1 = __floats2half2_rn(v.z, v.w);
            float2 a = __half22float2(h0);
            float2 b = __half22float2(h1);
            s  += (a.x + a.y) + (b.x + b.y);
            sq += a.x*a.x + a.y*a.y + b.x*b.x + b.y*b.y;
            xq[slice_v4 + off] = make_uint2(h2u(h0), h2u(h1));  // evict-normal: stays in L2
        }
    }

    #pragma unroll
    for (int o = 16; o > 0; o >>= 1) {
        s  += __shfl_down_sync(0xffffffffu, s,  o);
        sq += __shfl_down_sync(0xffffffffu, sq, o);
    }
    __shared__ float sh_s[RTHREADS / 32], sh_q[RTHREADS / 32];
    const int lane = tid & 31, w = tid >> 5;
    if (lane == 0) { sh_s[w] = s; sh_q[w] = sq; }
    __syncthreads();
    if (w == 0) {
        s  = (lane < RTHREADS / 32) ? sh_s[lane] : 0.f;
        sq = (lane < RTHREADS / 32) ? sh_q[lane] : 0.f;
        #pragma unroll
        for (int o = 4; o > 0; o >>= 1) {
            s  += __shfl_down_sync(0xffffffffu, s,  o);
            sq += __shfl_down_sync(0xffffffffu, sq, o);
        }
        if (lane == 0) {
            g_psum[c * BPC + bx] = s;
            g_psq [c * BPC + bx] = sq;
        }
    }
}

// ---------------- Pass 2: per-channel stats -> params ----------------
__global__ void qbn_finalize(const float* __restrict__ weight,
                             const float* __restrict__ bias) {
    const int c    = blockIdx.x;
    const int lane = threadIdx.x;   // 32 threads
    float s  = g_psum[c * BPC + lane];
    float sq = g_psq [c * BPC + lane];
    #pragma unroll
    for (int o = 16; o > 0; o >>= 1) {
        s  += __shfl_down_sync(0xffffffffu, s,  o);
        sq += __shfl_down_sync(0xffffffffu, sq, o);
    }
    if (lane == 0) {
        const float inv_n = 1.0f / (float)CPC;
        float mean = s * inv_n;
        float var  = sq * inv_n - mean * mean;
        float mean_q  = fq1(mean);
        float var_q   = fq1(var);
        float inv_std = 1.0f / sqrtf(var_q + 1e-5f);
        float w_q     = fq1(weight[c]);
        float b_q     = fq1(bias[c]);
        g_params[c] = make_float4(mean_q, inv_std, w_q, b_q);
    }
}

// ------- Pass 3: read fp16 x_q (L2-resident), normalize+quant, discard lines -------
__global__ void __launch_bounds__(256) qbn_apply(float* __restrict__ out) {
    __shared__ float4 sp[NC];
    if (threadIdx.x < NC) sp[threadIdx.x] = g_params[threadIdx.x];
    __syncthreads();

    const uint4* xq4 = reinterpret_cast<const uint4*>(g_xq);   // 8 halves per uint4
    float4*      yo  = reinterpret_cast<float4*>(out);
    const char*  xqb = reinterpret_cast<const char*>(g_xq);

    const int stride = gridDim.x * blockDim.x;
    const int base   = blockIdx.x * blockDim.x + threadIdx.x;

    // Backward walk: most-recently-written (hottest in L2) groups first.
    for (int ur = base; ur < NGROUPS; ur += stride) {
        const int u = NGROUPS - 1 - ur;
        const int c = (u >> 14) & (NC - 1);      // 2^14 groups per (n,c) slice
        const float4 p = sp[c];                  // {mean, inv_std, w, b}

        uint4 q = xq4[u];
        float2 a0 = __half22float2(u2h(q.x));
        float2 a1 = __half22float2(u2h(q.y));
        float2 a2 = __half22float2(u2h(q.z));
        float2 a3 = __half22float2(u2h(q.w));

        // Each 128B line = 8 consecutive u within this warp; drop it after all
        // lanes have loaded (no DRAM writeback of the scratch buffer).
        __syncwarp();
        if ((u & 7) == 0) {
            asm volatile("discard.global.L2 [%0], 128;"
                         :: "l"(xqb + (size_t)u * 16) : "memory");
        }

        float y0 = fmaf(p.z, (a0.x - p.x) * p.y, p.w);
        float y1 = fmaf(p.z, (a0.y - p.x) * p.y, p.w);
        float y2 = fmaf(p.z, (a1.x - p.x) * p.y, p.w);
        float y3 = fmaf(p.z, (a1.y - p.x) * p.y, p.w);
        float y4 = fmaf(p.z, (a2.x - p.x) * p.y, p.w);
        float y5 = fmaf(p.z, (a2.y - p.x) * p.y, p.w);
        float y6 = fmaf(p.z, (a3.x - p.x) * p.y, p.w);
        float y7 = fmaf(p.z, (a3.y - p.x) * p.y, p.w);

        float2 q0 = fq2(y0, y1);
        float2 q1 = fq2(y2, y3);
        float2 q2 = fq2(y4, y5);
        float2 q3 = fq2(y6, y7);

        __stcs(yo + 2 * u,     make_float4(q0.x, q0.y, q1.x, q1.y));
        __stcs(yo + 2 * u + 1, make_float4(q2.x, q2.y, q3.x, q3.y));
    }
}

extern "C" void kernel_launch(void* const* d_in, const int* in_sizes, int n_in,
                              void* d_out, int out_size) {
    const float* x      = (const float*)d_in[0];
    const float* weight = (const float*)d_in[1];
    const float* bias   = (const float*)d_in[2];
    float* out = (float*)d_out;

    dim3 rgrid(BPC, NC);
    qbn_reduce  <<<rgrid, RTHREADS>>>(x);
    qbn_finalize<<<NC, 32>>>(weight, bias);
    qbn_apply   <<<2048, 256>>>(out);
}

// round 4
// speedup vs baseline: 3.0017x; 3.0017x over previous
#include <cuda_runtime.h>
#include <cuda_fp16.h>

// QuantizedBatchNorm3d: x [8,64,32,64,64] fp32, weight[64], bias[64] -> y same shape.
// fake_quant(exp=5, sig=10, RNE) == IEEE fp16 round-trip for all reachable values.
//
// R4: reduce blocks map to CONTIGUOUS 128KB address chunks in bid order, so the
// last-running blocks read the highest addresses -> L2 ends holding a coherent
// ~126MB tail of x (clean lines). Apply walks backward from the top to harvest
// those hits before they evict. Streaming stores keep output from polluting.

#define NB        8
#define NC        64
#define SPATIAL   (32*64*64)            // 2^17 elements per (n,c) slice
#define CPC       (NB*SPATIAL)          // 2^20 elements per channel
#define TOTAL_V4  (1 << 24)             // 2^26 elements / 4
#define NBLOCKS   2048                  // reduce blocks, 8192 float4 each
#define RTHREADS  256

__device__ float  g_psum[NC * 32];
__device__ float  g_psq [NC * 32];
__device__ float4 g_params[NC];         // {mean_q, inv_std, w_q, b_q}

__device__ __forceinline__ float fq1(float v) {
    return __half2float(__float2half_rn(v));
}
__device__ __forceinline__ float2 fq2(float a, float b) {
    __half2 h = __floats2half2_rn(a, b);
    return __half22float2(h);
}

// ------- Pass 1: per-channel sum/sumsq of fq(x), contiguous-chunk blocks -------
// Block b covers float4 range [b*8192, (b+1)*8192). Since a (n,c) slice is
// 32768 float4, 4 consecutive blocks cover one slice: c = (b>>2)&63.
__global__ void __launch_bounds__(RTHREADS) qbn_reduce(const float* __restrict__ x) {
    const int b   = blockIdx.x;
    const int tid = threadIdx.x;
    const float4* p = reinterpret_cast<const float4*>(x) + (size_t)b * 8192;

    float s = 0.f, sq = 0.f;
    #pragma unroll
    for (int i = 0; i < 32; i++) {
        float4 v = p[i * RTHREADS + tid];
        float2 a = fq2(v.x, v.y);
        float2 c2 = fq2(v.z, v.w);
        s  += (a.x + a.y) + (c2.x + c2.y);
        sq += a.x*a.x + a.y*a.y + c2.x*c2.x + c2.y*c2.y;
    }

    #pragma unroll
    for (int o = 16; o > 0; o >>= 1) {
        s  += __shfl_down_sync(0xffffffffu, s,  o);
        sq += __shfl_down_sync(0xffffffffu, sq, o);
    }
    __shared__ float sh_s[RTHREADS / 32], sh_q[RTHREADS / 32];
    const int lane = tid & 31, w = tid >> 5;
    if (lane == 0) { sh_s[w] = s; sh_q[w] = sq; }
    __syncthreads();
    if (w == 0) {
        s  = (lane < RTHREADS / 32) ? sh_s[lane] : 0.f;
        sq = (lane < RTHREADS / 32) ? sh_q[lane] : 0.f;
        #pragma unroll
        for (int o = 4; o > 0; o >>= 1) {
            s  += __shfl_down_sync(0xffffffffu, s,  o);
            sq += __shfl_down_sync(0xffffffffu, sq, o);
        }
        if (lane == 0) {
            const int c     = (b >> 2) & (NC - 1);
            const int part  = ((b >> 8) << 2) | (b & 3);   // n*4 + piece, 0..31
            g_psum[c * 32 + part] = s;
            g_psq [c * 32 + part] = sq;
        }
    }
}

// ---------------- Pass 2: per-channel stats -> params ----------------
__global__ void qbn_finalize(const float* __restrict__ weight,
                             const float* __restrict__ bias) {
    const int c    = blockIdx.x;
    const int lane = threadIdx.x;   // 32 threads
    float s  = g_psum[c * 32 + lane];
    float sq = g_psq [c * 32 + lane];
    #pragma unroll
    for (int o = 16; o > 0; o >>= 1) {
        s  += __shfl_down_sync(0xffffffffu, s,  o);
        sq += __shfl_down_sync(0xffffffffu, sq, o);
    }
    if (lane == 0) {
        const float inv_n = 1.0f / (float)CPC;
        float mean = s * inv_n;
        float var  = sq * inv_n - mean * mean;
        float mean_q  = fq1(mean);
        float var_q   = fq1(var);
        float inv_std = 1.0f / sqrtf(var_q + 1e-5f);
        float w_q     = fq1(weight[c]);
        float b_q     = fq1(bias[c]);
        g_params[c] = make_float4(mean_q, inv_std, w_q, b_q);
    }
}

// ---------------- Pass 3: normalize + final quant (backward walk) ----------------
__global__ void __launch_bounds__(256) qbn_apply(const float* __restrict__ x,
                                                 float* __restrict__ out) {
    __shared__ float4 sp[NC];
    if (threadIdx.x < NC) sp[threadIdx.x] = g_params[threadIdx.x];
    __syncthreads();

    const float4* xin = reinterpret_cast<const float4*>(x);
    float4*       yo  = reinterpret_cast<float4*>(out);

    const int stride = gridDim.x * blockDim.x;
    const int base   = blockIdx.x * blockDim.x + threadIdx.x;

    // Descend from the top of x: the highest addresses are the freshest
    // (coherent) L2 content left by the bid-ordered reduce pass.
    for (int vr = base; vr < TOTAL_V4; vr += stride) {
        const int v = TOTAL_V4 - 1 - vr;
        const int c = (v >> 15) & (NC - 1);     // 2^15 float4 per (n,c) slice
        const float4 p = sp[c];                 // {mean, inv_std, w, b}
        float4 xv = __ldcs(xin + v);            // dead after read: evict-first
        float2 a = fq2(xv.x, xv.y);
        float2 b = fq2(xv.z, xv.w);
        float y0 = fmaf(p.z, (a.x - p.x) * p.y, p.w);
        float y1 = fmaf(p.z, (a.y - p.x) * p.y, p.w);
        float y2 = fmaf(p.z, (b.x - p.x) * p.y, p.w);
        float y3 = fmaf(p.z, (b.y - p.x) * p.y, p.w);
        float2 q0 = fq2(y0, y1);
        float2 q1 = fq2(y2, y3);
        __stcs(yo + v, make_float4(q0.x, q0.y, q1.x, q1.y));
    }
}

extern "C" void kernel_launch(void* const* d_in, const int* in_sizes, int n_in,
                              void* d_out, int out_size) {
    const float* x      = (const float*)d_in[0];
    const float* weight = (const float*)d_in[1];
    const float* bias   = (const float*)d_in[2];
    float* out = (float*)d_out;

    qbn_reduce  <<<NBLOCKS, RTHREADS>>>(x);
    qbn_finalize<<<NC, 32>>>(weight, bias);
    qbn_apply   <<<2048, 256>>>(x, out);
}

// round 5
// speedup vs baseline: 3.1466x; 1.0482x over previous
#include <cuda_runtime.h>
#include <cuda_fp16.h>

// QuantizedBatchNorm3d: x [8,64,32,64,64] fp32, weight[64], bias[64] -> y same shape.
// fake_quant(exp=5, sig=10, RNE) == IEEE fp16 round-trip for all reachable values.
//
// R5: apply pass rebuilt for bandwidth: exact partition (8192 blocks x 256 thr),
// 8 float4 per thread with all 8 loads front-batched (MLP=8), channel constant
// per block (chunk-aligned), zero per-element index math. ldcs/stcs policies kept.

#define NB        8
#define NC        64
#define SPATIAL   (32*64*64)            // 2^17 elements per (n,c) slice
#define CPC       (NB*SPATIAL)          // 2^20 elements per channel
#define TOTAL_V4  (1 << 24)             // 2^26 elements / 4
#define NBLOCKS   2048                  // reduce blocks, 8192 float4 each
#define RTHREADS  256

#define ABLOCKS   8192                  // apply blocks
#define ACHUNK    2048                  // float4 per apply block (2048 | 32768)

__device__ float  g_psum[NC * 32];
__device__ float  g_psq [NC * 32];
__device__ float4 g_params[NC];         // {mean_q, inv_std, w_q, b_q}

__device__ __forceinline__ float fq1(float v) {
    return __half2float(__float2half_rn(v));
}
__device__ __forceinline__ float2 fq2(float a, float b) {
    __half2 h = __floats2half2_rn(a, b);
    return __half22float2(h);
}

// ------- Pass 1: per-channel sum/sumsq of fq(x), contiguous-chunk blocks -------
__global__ void __launch_bounds__(RTHREADS) qbn_reduce(const float* __restrict__ x) {
    const int b   = blockIdx.x;
    const int tid = threadIdx.x;
    const float4* p = reinterpret_cast<const float4*>(x) + (size_t)b * 8192;

    float s = 0.f, sq = 0.f;
    #pragma unroll
    for (int i = 0; i < 32; i++) {
        float4 v = p[i * RTHREADS + tid];
        float2 a  = fq2(v.x, v.y);
        float2 c2 = fq2(v.z, v.w);
        s  += (a.x + a.y) + (c2.x + c2.y);
        sq += a.x*a.x + a.y*a.y + c2.x*c2.x + c2.y*c2.y;
    }

    #pragma unroll
    for (int o = 16; o > 0; o >>= 1) {
        s  += __shfl_down_sync(0xffffffffu, s,  o);
        sq += __shfl_down_sync(0xffffffffu, sq, o);
    }
    __shared__ float sh_s[RTHREADS / 32], sh_q[RTHREADS / 32];
    const int lane = tid & 31, w = tid >> 5;
    if (lane == 0) { sh_s[w] = s; sh_q[w] = sq; }
    __syncthreads();
    if (w == 0) {
        s  = (lane < RTHREADS / 32) ? sh_s[lane] : 0.f;
        sq = (lane < RTHREADS / 32) ? sh_q[lane] : 0.f;
        #pragma unroll
        for (int o = 4; o > 0; o >>= 1) {
            s  += __shfl_down_sync(0xffffffffu, s,  o);
            sq += __shfl_down_sync(0xffffffffu, sq, o);
        }
        if (lane == 0) {
            const int c    = (b >> 2) & (NC - 1);
            const int part = ((b >> 8) << 2) | (b & 3);   // n*4 + piece, 0..31
            g_psum[c * 32 + part] = s;
            g_psq [c * 32 + part] = sq;
        }
    }
}

// ---------------- Pass 2: per-channel stats -> params ----------------
__global__ void qbn_finalize(const float* __restrict__ weight,
                             const float* __restrict__ bias) {
    const int c    = blockIdx.x;
    const int lane = threadIdx.x;   // 32 threads
    float s  = g_psum[c * 32 + lane];
    float sq = g_psq [c * 32 + lane];
    #pragma unroll
    for (int o = 16; o > 0; o >>= 1) {
        s  += __shfl_down_sync(0xffffffffu, s,  o);
        sq += __shfl_down_sync(0xffffffffu, sq, o);
    }
    if (lane == 0) {
        const float inv_n = 1.0f / (float)CPC;
        float mean = s * inv_n;
        float var  = sq * inv_n - mean * mean;
        float mean_q  = fq1(mean);
        float var_q   = fq1(var);
        float inv_std = 1.0f / sqrtf(var_q + 1e-5f);
        float w_q     = fq1(weight[c]);
        float b_q     = fq1(bias[c]);
        g_params[c] = make_float4(mean_q, inv_std, w_q, b_q);
    }
}

// -------- Pass 3: normalize + final quant. 8 float4/thread, loads batched --------
__global__ void __launch_bounds__(RTHREADS) qbn_apply(const float* __restrict__ x,
                                                      float* __restrict__ out) {
    // Reverse macro order: highest chunks first (harmless; keeps R2's policy wins).
    const int cc   = (ABLOCKS - 1) - blockIdx.x;
    const int tid  = threadIdx.x;
    const size_t base = (size_t)cc * ACHUNK;

    // Channel constant for the whole block (ACHUNK divides the 32768-float4 slice).
    const int c = (int)((base >> 15) & (NC - 1));
    const float4 p = g_params[c];               // {mean, inv_std, w, b}

    const float4* xin = reinterpret_cast<const float4*>(x) + base;
    float4*       yo  = reinterpret_cast<float4*>(out) + base;

    // Front-batch all 8 loads: MLP = 8 per thread.
    float4 v[8];
    #pragma unroll
    for (int k = 0; k < 8; k++)
        v[k] = __ldcs(xin + tid + k * RTHREADS);

    #pragma unroll
    for (int k = 0; k < 8; k++) {
        float2 a = fq2(v[k].x, v[k].y);
        float2 b = fq2(v[k].z, v[k].w);
        float y0 = fmaf(p.z, (a.x - p.x) * p.y, p.w);
        float y1 = fmaf(p.z, (a.y - p.x) * p.y, p.w);
        float y2 = fmaf(p.z, (b.x - p.x) * p.y, p.w);
        float y3 = fmaf(p.z, (b.y - p.x) * p.y, p.w);
        float2 q0 = fq2(y0, y1);
        float2 q1 = fq2(y2, y3);
        __stcs(yo + tid + k * RTHREADS, make_float4(q0.x, q0.y, q1.x, q1.y));
    }
}

extern "C" void kernel_launch(void* const* d_in, const int* in_sizes, int n_in,
                              void* d_out, int out_size) {
    const float* x      = (const float*)d_in[0];
    const float* weight = (const float*)d_in[1];
    const float* bias   = (const float*)d_in[2];
    float* out = (float*)d_out;

    qbn_reduce  <<<NBLOCKS, RTHREADS>>>(x);
    qbn_finalize<<<NC, 32>>>(weight, bias);
    qbn_apply   <<<ABLOCKS, RTHREADS>>>(x, out);
}